// round 15
// baseline (speedup 1.0000x reference)
#include <cuda_runtime.h>
#include <math.h>

#define N2 512
#define DM 256
#define NSPLIT 8
#define KS 32        // k-width per split chunk
#define NT 16        // 16 tiles of 32 per dim; symmetric pairs = 136
#define GRID1 1088   // 136 pairs x 8 splits

__device__ float g_gram[NSPLIT][N2 * N2];
__device__ float g_norm[N2];
__device__ float g_ts[N2];
__device__ int   g_perm[N2];
__device__ float g_part[N2];

// ---------------------------------------------------------------------------
// K1: symmetric split-k Gram. 136 pairs (32x32 tiles) x 8 splits = 1088 blocks
// x 256 threads, 2x2 microtile, rotated-transpose SMEM. High residency
// (~7 CTA/SM) is the point: latency-bound phases need threads.
// ---------------------------------------------------------------------------
__global__ void __launch_bounds__(256) dist_kernel(
    const float* __restrict__ E, const float* __restrict__ T)
{
    __shared__ float At[KS][34];
    __shared__ float Bt[KS][34];

    const int tid  = threadIdx.x;
    const int lane = tid & 31;
    const int w    = tid >> 5;

    // ---- fused rank-by-count + row norm on warp 0 of blocks 0..511 ----
    if (w == 0 && blockIdx.x < N2) {
        const int e = blockIdx.x;
        const float tv = __ldg(&T[e]);
        int cnt = 0;
        float nrm = 0.0f;
        #pragma unroll
        for (int c = 0; c < 16; c++) {
            int jj = lane + c * 32;
            float o = __ldg(&T[jj]);
            cnt += (o < tv || (o == tv && jj < e)) ? 1 : 0;
            if (c < 8) {
                float v = __ldg(&E[e * DM + jj]);
                nrm = fmaf(v, v, nrm);
            }
        }
        #pragma unroll
        for (int o = 16; o > 0; o >>= 1) {
            cnt += __shfl_xor_sync(0xffffffffu, cnt, o);
            nrm += __shfl_xor_sync(0xffffffffu, nrm, o);
        }
        if (lane == 0) { g_ts[cnt] = tv; g_perm[cnt] = e; g_norm[e] = nrm; }
    }

    // ---- decode block -> (pair a<=b over 16 tiles, split 0..7) ----
    const int pr    = blockIdx.x >> 3;
    const int split = blockIdx.x & 7;
    int a = 0, rem = pr, len = NT;
    while (rem >= len) { rem -= len; a++; len--; }
    const int b = a + rem;
    const int kbase = split * KS;

    // ---- loaders: r = row (0..31), cq = k-quarter (0..7), 1 float4 each ----
    const int r  = tid >> 3;
    const int cq = tid & 7;
    float4 av4 = *reinterpret_cast<const float4*>(E + (a * 32 + r) * DM + kbase + cq * 4);
    float4 bv4 = *reinterpret_cast<const float4*>(E + (b * 32 + r) * DM + kbase + cq * 4);

#define ST_A(k, val) At[(k)][(r + 8 * ((k) >> 3)) & 31] = (val)
#define ST_B(k, val) Bt[(k)][(r + 8 * ((k) >> 3)) & 31] = (val)
    {
        const int k1 = cq * 4;
        ST_A(k1 + 0, av4.x); ST_A(k1 + 1, av4.y);
        ST_A(k1 + 2, av4.z); ST_A(k1 + 3, av4.w);
        ST_B(k1 + 0, bv4.x); ST_B(k1 + 1, bv4.y);
        ST_B(k1 + 2, bv4.z); ST_B(k1 + 3, bv4.w);
    }
    __syncthreads();

    // ---- compute: 2x2 microtile, 16x16 thread grid ----
    const int tx = tid & 15, ty = tid >> 4;
    float a00 = 0.f, a01 = 0.f, a10 = 0.f, a11 = 0.f;

    #pragma unroll
    for (int kk = 0; kk < KS; kk++) {
        const int rot = 8 * (kk >> 3);
        float2 x = *reinterpret_cast<const float2*>(&At[kk][(2 * ty + rot) & 31]);
        float2 y = *reinterpret_cast<const float2*>(&Bt[kk][(2 * tx + rot) & 31]);
        a00 = fmaf(x.x, y.x, a00);
        a01 = fmaf(x.x, y.y, a01);
        a10 = fmaf(x.y, y.x, a10);
        a11 = fmaf(x.y, y.y, a11);
    }

    float* G = g_gram[split];
    const int gi = a * 32 + 2 * ty, gj = b * 32 + 2 * tx;
    float2 v;
    v.x = a00; v.y = a01;
    *reinterpret_cast<float2*>(&G[(gi    ) * N2 + gj]) = v;
    v.x = a10; v.y = a11;
    *reinterpret_cast<float2*>(&G[(gi + 1) * N2 + gj]) = v;
    if (a != b) {
        v.x = a00; v.y = a10;
        *reinterpret_cast<float2*>(&G[(gj    ) * N2 + gi]) = v;
        v.x = a01; v.y = a11;
        *reinterpret_cast<float2*>(&G[(gj + 1) * N2 + gi]) = v;
    }
}

// ---------------------------------------------------------------------------
// K2: per-row loss, 512 threads/block, ONE sorted element per thread.
// ---------------------------------------------------------------------------
__global__ void __launch_bounds__(512) loss_kernel(const float* __restrict__ T)
{
    __shared__ float drow[N2], ts[N2], ds[N2], sv[N2];
    __shared__ float psX[N2 + 1], ssX[N2 + 1];
    __shared__ float wtot[16];
    __shared__ float red[16];
    __shared__ int   ri_sh;

    const int i = blockIdx.x, t = threadIdx.x, lane = t & 31, w = t >> 5;
    const float ni = __ldg(&g_norm[i]);

    // dist row by ORIGINAL index e = t (coalesced over splits)
    {
        float gsum = 0.0f;
        #pragma unroll
        for (int s = 0; s < NSPLIT; s++)
            gsum += __ldg(&g_gram[s][i * N2 + t]);
        float ne = __ldg(&g_norm[t]);
        drow[t] = sqrtf(fmaxf(ni + ne - 2.0f * gsum, 0.0f));
        ts[t]   = g_ts[t];
    }
    __syncthreads();

    const float ti = __ldg(&T[i]);

    {
        int p = g_perm[t];
        float d = drow[p];
        ds[t] = d;
        if (p == i) { sv[t] = 1.0f; ri_sh = t; }
        else        { sv[t] = __expf(-d); }
    }
    __syncthreads();

    // ---- dual scan, additions only (thread owns sorted element t) ----
    const float v0 = sv[t];
    float p = v0;
    #pragma unroll
    for (int off = 1; off < 32; off <<= 1) {
        float tmp = __shfl_up_sync(0xffffffffu, p, off);
        if (lane >= off) p += tmp;
    }
    float q = v0;
    #pragma unroll
    for (int off = 1; off < 32; off <<= 1) {
        float tmp = __shfl_down_sync(0xffffffffu, q, off);
        if (lane + off < 32) q += tmp;
    }
    if (lane == 31) wtot[w] = p;
    __syncthreads();

    float offp = 0.0f, offs = 0.0f, total = 0.0f;
    #pragma unroll
    for (int ww = 0; ww < 16; ww++) {
        float tw = wtot[ww];
        total += tw;
        if (ww < w) offp += tw;
        if (ww > w) offs += tw;
    }
    psX[t + 1] = offp + p;      // inclusive prefix of first t+1
    ssX[t]     = offs + q;      // inclusive suffix from t
    if (t == 0) { psX[0] = 0.0f; ssX[N2] = 0.0f; }
    __syncthreads();

    const int ri = ri_sh;

    // ---- branchless counting searches (R12-proven, with R probe fix) ----
    const int r = t;
    const float ak = fabsf(ti - ts[r]);
    int L = 0, R = 0;
    #pragma unroll
    for (int step = 256; step > 0; step >>= 1) {
        if (ti - ts[L + step - 1] >= ak) L += step;
        if (ts[R + step - 1] - ti <  ak) R += step;
    }
    if (ts[R] - ti < ak) R++;       // steps sum to 511; R may be 512
    float denom = psX[L] + ssX[R];
    if (ak == 0.0f) denom = total - 1.0f;
    float local = (r != ri) ? (ds[r] + __logf(denom)) : 0.0f;

    #pragma unroll
    for (int o = 16; o > 0; o >>= 1)
        local += __shfl_xor_sync(0xffffffffu, local, o);
    if (lane == 0) red[w] = local;
    __syncthreads();
    if (t == 0) {
        float sum = 0.0f;
        #pragma unroll
        for (int k = 0; k < 16; k++) sum += red[k];
        g_part[i] = sum;
    }
}

// ---------------------------------------------------------------------------
// K3: final reduce of 512 partials -> scalar
// ---------------------------------------------------------------------------
__global__ void __launch_bounds__(256) reduce_kernel(float* __restrict__ out)
{
    __shared__ float red[8];
    const int t = threadIdx.x, lane = t & 31, w = t >> 5;
    float v = g_part[t] + g_part[t + 256];
    #pragma unroll
    for (int o = 16; o > 0; o >>= 1)
        v += __shfl_xor_sync(0xffffffffu, v, o);
    if (lane == 0) red[w] = v;
    __syncthreads();
    if (t == 0) {
        float sum = 0.0f;
        #pragma unroll
        for (int k = 0; k < 8; k++) sum += red[k];
        const float scale = 1.0f / (float(N2) * float(N2 - 1));
        *out = sum * scale;
    }
}

extern "C" void kernel_launch(void* const* d_in, const int* in_sizes, int n_in,
                              void* d_out, int out_size) {
    const float* E = (const float*)d_in[0];   // embeddings [512,256]
    const float* T = (const float*)d_in[1];   // targets    [512]
    float* out = (float*)d_out;

    dist_kernel<<<GRID1, 256>>>(E, T);
    loss_kernel<<<N2, 512>>>(T);
    reduce_kernel<<<1, 256>>>(out);
}

// round 16
// speedup vs baseline: 1.1407x; 1.1407x over previous
#include <cuda_runtime.h>
#include <math.h>

#define N2 512
#define DM 256
#define NSPLIT 4
#define KS 64        // k-width per split chunk
#define NT 16        // 16 tiles of 32 per dim; symmetric pairs = 136
#define GRID1 544    // 136 pairs x 4 splits

__device__ float g_gram[NSPLIT][N2 * N2];
__device__ float g_norm[N2];
__device__ float g_ts[N2];
__device__ int   g_perm[N2];
__device__ float g_part[N2];
__device__ unsigned g_done = 0;   // last-block ticket (wraps to 0 -> replay-safe)

// ---------------------------------------------------------------------------
// K1: symmetric split-k Gram. 136 pairs (32x32 tiles) x 4 splits (k=64) = 544
// blocks x 256 threads, 2x2 microtile, rotated-transpose SMEM, ONE barrier.
// ---------------------------------------------------------------------------
__global__ void __launch_bounds__(256) dist_kernel(
    const float* __restrict__ E, const float* __restrict__ T)
{
    __shared__ float At[KS][34];
    __shared__ float Bt[KS][34];

    const int tid  = threadIdx.x;
    const int lane = tid & 31;
    const int w    = tid >> 5;

    // ---- fused rank-by-count + row norm on warp 0 of blocks 0..511 ----
    if (w == 0 && blockIdx.x < N2) {
        const int e = blockIdx.x;
        const float tv = __ldg(&T[e]);
        int cnt = 0;
        float nrm = 0.0f;
        #pragma unroll
        for (int c = 0; c < 16; c++) {
            int jj = lane + c * 32;
            float o = __ldg(&T[jj]);
            cnt += (o < tv || (o == tv && jj < e)) ? 1 : 0;
            if (c < 8) {
                float v = __ldg(&E[e * DM + jj]);
                nrm = fmaf(v, v, nrm);
            }
        }
        #pragma unroll
        for (int o = 16; o > 0; o >>= 1) {
            cnt += __shfl_xor_sync(0xffffffffu, cnt, o);
            nrm += __shfl_xor_sync(0xffffffffu, nrm, o);
        }
        if (lane == 0) { g_ts[cnt] = tv; g_perm[cnt] = e; g_norm[e] = nrm; }
    }

    // ---- decode block -> (pair a<=b over 16 tiles, split 0..3) ----
    const int pr    = blockIdx.x >> 2;
    const int split = blockIdx.x & 3;
    int a = 0, rem = pr, len = NT;
    while (rem >= len) { rem -= len; a++; len--; }
    const int b = a + rem;
    const int kbase = split * KS;

    // ---- loaders: r = row (0..31), cq = k-octet (0..7), 2 float4 each ----
    const int r  = tid >> 3;
    const int cq = tid & 7;
    const float* Ea = E + (a * 32 + r) * DM + kbase + cq * 8;
    const float* Eb = E + (b * 32 + r) * DM + kbase + cq * 8;
    float4 a1 = *reinterpret_cast<const float4*>(Ea);
    float4 a2 = *reinterpret_cast<const float4*>(Ea + 4);
    float4 b1 = *reinterpret_cast<const float4*>(Eb);
    float4 b2 = *reinterpret_cast<const float4*>(Eb + 4);

#define ST_A(k, val) At[(k)][(r + 8 * ((k) >> 3)) & 31] = (val)
#define ST_B(k, val) Bt[(k)][(r + 8 * ((k) >> 3)) & 31] = (val)
    {
        const int k1 = cq * 8;
        ST_A(k1 + 0, a1.x); ST_A(k1 + 1, a1.y);
        ST_A(k1 + 2, a1.z); ST_A(k1 + 3, a1.w);
        ST_A(k1 + 4, a2.x); ST_A(k1 + 5, a2.y);
        ST_A(k1 + 6, a2.z); ST_A(k1 + 7, a2.w);
        ST_B(k1 + 0, b1.x); ST_B(k1 + 1, b1.y);
        ST_B(k1 + 2, b1.z); ST_B(k1 + 3, b1.w);
        ST_B(k1 + 4, b2.x); ST_B(k1 + 5, b2.y);
        ST_B(k1 + 6, b2.z); ST_B(k1 + 7, b2.w);
    }
    __syncthreads();

    // ---- compute: 2x2 microtile, 16x16 thread grid, 64 k-iters ----
    const int tx = tid & 15, ty = tid >> 4;
    float a00 = 0.f, a01 = 0.f, a10 = 0.f, a11 = 0.f;

    #pragma unroll
    for (int kk = 0; kk < KS; kk++) {
        const int rot = 8 * (kk >> 3);
        float2 x = *reinterpret_cast<const float2*>(&At[kk][(2 * ty + rot) & 31]);
        float2 y = *reinterpret_cast<const float2*>(&Bt[kk][(2 * tx + rot) & 31]);
        a00 = fmaf(x.x, y.x, a00);
        a01 = fmaf(x.x, y.y, a01);
        a10 = fmaf(x.y, y.x, a10);
        a11 = fmaf(x.y, y.y, a11);
    }

    float* G = g_gram[split];
    const int gi = a * 32 + 2 * ty, gj = b * 32 + 2 * tx;
    float2 v;
    v.x = a00; v.y = a01;
    *reinterpret_cast<float2*>(&G[(gi    ) * N2 + gj]) = v;
    v.x = a10; v.y = a11;
    *reinterpret_cast<float2*>(&G[(gi + 1) * N2 + gj]) = v;
    if (a != b) {
        v.x = a00; v.y = a10;
        *reinterpret_cast<float2*>(&G[(gj    ) * N2 + gi]) = v;
        v.x = a01; v.y = a11;
        *reinterpret_cast<float2*>(&G[(gj + 1) * N2 + gi]) = v;
    }
}

// ---------------------------------------------------------------------------
// K2: per-row loss (512 thr, 1 sorted elem/thread) + fused last-block reduce.
// ---------------------------------------------------------------------------
__global__ void __launch_bounds__(512) loss_kernel(
    const float* __restrict__ T, float* __restrict__ out)
{
    __shared__ float drow[N2], ts[N2], ds[N2], sv[N2];
    __shared__ float psX[N2 + 1], ssX[N2 + 1];
    __shared__ float wtot[16];
    __shared__ float red[16];
    __shared__ int   ri_sh;
    __shared__ int   is_last;

    const int i = blockIdx.x, t = threadIdx.x, lane = t & 31, w = t >> 5;
    const float ni = __ldg(&g_norm[i]);

    // dist row by ORIGINAL index e = t (coalesced over splits)
    {
        float gsum = 0.0f;
        #pragma unroll
        for (int s = 0; s < NSPLIT; s++)
            gsum += __ldg(&g_gram[s][i * N2 + t]);
        float ne = __ldg(&g_norm[t]);
        drow[t] = sqrtf(fmaxf(ni + ne - 2.0f * gsum, 0.0f));
        ts[t]   = g_ts[t];
    }
    __syncthreads();

    const float ti = __ldg(&T[i]);

    {
        int p = g_perm[t];
        float d = drow[p];
        ds[t] = d;
        if (p == i) { sv[t] = 1.0f; ri_sh = t; }
        else        { sv[t] = __expf(-d); }
    }
    __syncthreads();

    // ---- dual scan, additions only (thread owns sorted element t) ----
    const float v0 = sv[t];
    float p = v0;
    #pragma unroll
    for (int off = 1; off < 32; off <<= 1) {
        float tmp = __shfl_up_sync(0xffffffffu, p, off);
        if (lane >= off) p += tmp;
    }
    float q = v0;
    #pragma unroll
    for (int off = 1; off < 32; off <<= 1) {
        float tmp = __shfl_down_sync(0xffffffffu, q, off);
        if (lane + off < 32) q += tmp;
    }
    if (lane == 31) wtot[w] = p;
    __syncthreads();

    float offp = 0.0f, offs = 0.0f, total = 0.0f;
    #pragma unroll
    for (int ww = 0; ww < 16; ww++) {
        float tw = wtot[ww];
        total += tw;
        if (ww < w) offp += tw;
        if (ww > w) offs += tw;
    }
    psX[t + 1] = offp + p;      // inclusive prefix of first t+1
    ssX[t]     = offs + q;      // inclusive suffix from t
    if (t == 0) { psX[0] = 0.0f; ssX[N2] = 0.0f; }
    __syncthreads();

    const int ri = ri_sh;

    // ---- branchless counting searches (with the R-probe fix) ----
    const float ak = fabsf(ti - ts[t]);
    int L = 0, R = 0;
    #pragma unroll
    for (int step = 256; step > 0; step >>= 1) {
        if (ti - ts[L + step - 1] >= ak) L += step;
        if (ts[R + step - 1] - ti <  ak) R += step;
    }
    if (ts[R] - ti < ak) R++;       // steps sum to 511; R may be 512
    float denom = psX[L] + ssX[R];
    if (ak == 0.0f) denom = total - 1.0f;
    float local = (t != ri) ? (ds[t] + __logf(denom)) : 0.0f;

    #pragma unroll
    for (int o = 16; o > 0; o >>= 1)
        local += __shfl_xor_sync(0xffffffffu, local, o);
    if (lane == 0) red[w] = local;
    __syncthreads();
    if (t == 0) {
        float sum = 0.0f;
        #pragma unroll
        for (int k = 0; k < 16; k++) sum += red[k];
        g_part[i] = sum;
        __threadfence();
        unsigned ticket = atomicInc(&g_done, N2 - 1);  // wraps to 0 after 512th
        is_last = (ticket == N2 - 1) ? 1 : 0;
    }
    __syncthreads();

    // ---- last arriving block reduces all partials (fixed order: deterministic) ----
    if (is_last) {
        float v = *((volatile float*)&g_part[t]);
        #pragma unroll
        for (int o = 16; o > 0; o >>= 1)
            v += __shfl_xor_sync(0xffffffffu, v, o);
        if (lane == 0) red[w] = v;
        __syncthreads();
        if (t == 0) {
            float sum = 0.0f;
            #pragma unroll
            for (int k = 0; k < 16; k++) sum += red[k];
            const float scale = 1.0f / (float(N2) * float(N2 - 1));
            *out = sum * scale;
        }
    }
}

extern "C" void kernel_launch(void* const* d_in, const int* in_sizes, int n_in,
                              void* d_out, int out_size) {
    const float* E = (const float*)d_in[0];   // embeddings [512,256]
    const float* T = (const float*)d_in[1];   // targets    [512]
    float* out = (float*)d_out;

    dist_kernel<<<GRID1, 256>>>(E, T);
    loss_kernel<<<N2, 512>>>(T, out);
}